// round 16
// baseline (speedup 1.0000x reference)
#include <cuda_runtime.h>
#include <cuda_fp16.h>
#include <math.h>

#define W 160
#define H 160
#define D 160
#define PLANE (H * W)              // 25600
#define VOL (D * H * W)            // 4096000
#define INV_SZ (1.0f / 125.0f)

// Fused-stage tile: 32 x 8 outputs per plane, z-chunk of 8 (+2 halo each side)
#define TX2 32
#define TY2 8
#define HX2 36
#define HY2 12
#define ZC2 8
#define NPL (ZC2 + 4)              // 12 planes evaluated per block

// 4-field pack: p0 = (F,M) batch0, p1 = (F,M) batch1
struct __align__(8) H4 { __half2 p0, p1; };

// Scratch (__device__ globals: allocation-free rule)
__device__ H4 g_fm[VOL];
__device__ H4 g_s1[VOL];
__device__ H4 g_s2[VOL];
__device__ double g_acc;

__device__ __forceinline__ float frsqrt_approx(float x) {
    float y;
    asm("rsqrt.approx.f32 %0, %1;" : "=f"(y) : "f"(x));
    return y;
}
__device__ __forceinline__ int clampi(int v, int lo, int hi) {
    return v < lo ? lo : (v > hi ? hi : v);
}
__device__ __forceinline__ H4 h4add(H4 a, H4 b) {
    H4 r; r.p0 = __hadd2(a.p0, b.p0); r.p1 = __hadd2(a.p1, b.p1); return r;
}

__global__ void k_zero_acc() { g_acc = 0.0; }

// ---------------------------------------------------------------------------
// Loaders: (j, own). j = batch-0 voxel index; batch-1 lives at j + VOL.
struct LoadRaw4 {   // raw (F,M) pairs; populates fm cache at owned voxels
    const float* __restrict__ f;
    const float* __restrict__ m;
    H4* __restrict__ fm;
    __device__ __forceinline__ H4 operator()(int j, bool own) const {
        H4 r;
        r.p0 = __floats2half2_rn(f[j], m[j]);
        r.p1 = __floats2half2_rn(f[j + VOL], m[j + VOL]);
        if (own) fm[j] = r;
        return r;
    }
};
struct LoadG4 {     // (im - u)^2 per field
    const H4* __restrict__ fm;
    const H4* __restrict__ s1;
    __device__ __forceinline__ H4 operator()(int j, bool) const {
        H4 a = fm[j], u = s1[j], r;
        float2 v0 = __half22float2(a.p0), u0 = __half22float2(u.p0);
        float2 v1 = __half22float2(a.p1), u1 = __half22float2(u.p1);
        float d0x = v0.x - u0.x * INV_SZ, d0y = v0.y - u0.y * INV_SZ;
        float d1x = v1.x - u1.x * INV_SZ, d1y = v1.y - u1.y * INV_SZ;
        r.p0 = __floats2half2_rn(d0x * d0x, d0y * d0y);
        r.p1 = __floats2half2_rn(d1x * d1x, d1y * d1y);
        return r;
    }
};
struct LoadP4 {     // n_F * n_M per batch -> half2 (b0, b1)
    const H4* __restrict__ fm;
    const H4* __restrict__ s1;
    const H4* __restrict__ s2;
    __device__ __forceinline__ __half2 operator()(int j, bool) const {
        H4 a = fm[j], u = s1[j], v = s2[j];
        float2 a0 = __half22float2(a.p0), u0 = __half22float2(u.p0), v0 = __half22float2(v.p0);
        float2 a1 = __half22float2(a.p1), u1 = __half22float2(u.p1), v1 = __half22float2(v.p1);
        float pr0 = fmaxf((v0.x * INV_SZ) * (v0.y * INV_SZ), 1e-24f);
        float pr1 = fmaxf((v1.x * INV_SZ) * (v1.y * INV_SZ), 1e-24f);
        float p0 = (a0.x - u0.x * INV_SZ) * (a0.y - u0.y * INV_SZ) * frsqrt_approx(pr0);
        float p1 = (a1.x - u1.x * INV_SZ) * (a1.y - u1.y * INV_SZ) * frsqrt_approx(pr1);
        return __floats2half2_rn(p0, p1);
    }
};

// ---------------------------------------------------------------------------
// Fused 3D box stage (xy in smem per plane, z in rolling registers).
// Block = 256 threads; each thread owns one (tx, ty) output point.
// grid = (5, 20, 20) = 2000 blocks.
// Barrier pattern per plane (proven in R6 for correctness):
//   load -> sync -> x-box -> sync -> y-box. Exactly 2 barriers/plane.
template <class L>
__global__ void __launch_bounds__(256) k_stage_box(L ld, H4* __restrict__ out) {
    __shared__ H4 s_in[HY2][HX2 + 1];
    __shared__ H4 s_xr[HY2][TX2 + 1];

    const int gx0 = blockIdx.x * TX2;
    const int gy0 = blockIdx.y * TY2;
    const int z0  = blockIdx.z * ZC2;
    const int tid = threadIdx.x;
    const int tx = tid & 31;
    const int ty = tid >> 5;

    H4 p0, p1, p2, p3, p4;

    for (int ip = 0; ip < NPL; ip++) {
        const int zp = clampi(z0 - 2 + ip, 0, D - 1);
        const int zbase = zp * PLANE;
        const bool zowned = (ip >= 2) && (ip < 2 + ZC2);

        // Halo load: 432 evals, full block, coalesced rows.
        for (int i = tid; i < HY2 * HX2; i += 256) {
            int ly = i / HX2;
            int lx = i - ly * HX2;
            int gy = clampi(gy0 - 2 + ly, 0, H - 1);
            int gx = clampi(gx0 - 2 + lx, 0, W - 1);
            bool own = zowned && lx >= 2 && lx < HX2 - 2 && ly >= 2 && ly < HY2 - 2;
            s_in[ly][lx] = ld(zbase + gy * W + gx, own);
        }
        __syncthreads();

        // x-box: 12 rows x 32 cols = 384 tasks
        for (int i = tid; i < HY2 * TX2; i += 256) {
            int r = i >> 5;
            int x = i & 31;
            s_xr[r][x] = h4add(h4add(h4add(h4add(s_in[r][x], s_in[r][x + 1]),
                                           s_in[r][x + 2]), s_in[r][x + 3]),
                               s_in[r][x + 4]);
        }
        __syncthreads();

        // y-box: one point per thread
        H4 nw = h4add(h4add(h4add(h4add(s_xr[ty][tx], s_xr[ty + 1][tx]),
                                  s_xr[ty + 2][tx]), s_xr[ty + 3][tx]),
                      s_xr[ty + 4][tx]);
        p0 = p1; p1 = p2; p2 = p3; p3 = p4; p4 = nw;

        if (ip >= 4) {
            int z = z0 + ip - 4;
            H4 s = h4add(h4add(h4add(h4add(p0, p1), p2), p3), p4);
            out[z * PLANE + (gy0 + ty) * W + gx0 + tx] = s;
        }
    }
}

// Stage 3: fused 3D box of p = n_F*n_M (half2 batch pair) + masked reduction.
template <class L>
__global__ void __launch_bounds__(256) k_stage_reduce(L ld,
                                                      const float* __restrict__ mask) {
    __shared__ __half2 s_in[HY2][HX2 + 1];
    __shared__ __half2 s_xr[HY2][TX2 + 1];
    __shared__ double sred[256];

    const int gx0 = blockIdx.x * TX2;
    const int gy0 = blockIdx.y * TY2;
    const int z0  = blockIdx.z * ZC2;
    const int tid = threadIdx.x;
    const int tx = tid & 31;
    const int ty = tid >> 5;

    __half2 p0, p1, p2, p3, p4;
    double acc = 0.0;

    for (int ip = 0; ip < NPL; ip++) {
        const int zp = clampi(z0 - 2 + ip, 0, D - 1);
        const int zbase = zp * PLANE;

        for (int i = tid; i < HY2 * HX2; i += 256) {
            int ly = i / HX2;
            int lx = i - ly * HX2;
            int gy = clampi(gy0 - 2 + ly, 0, H - 1);
            int gx = clampi(gx0 - 2 + lx, 0, W - 1);
            s_in[ly][lx] = ld(zbase + gy * W + gx, false);
        }
        __syncthreads();

        for (int i = tid; i < HY2 * TX2; i += 256) {
            int r = i >> 5;
            int x = i & 31;
            s_xr[r][x] = __hadd2(__hadd2(__hadd2(__hadd2(s_in[r][x], s_in[r][x + 1]),
                                                 s_in[r][x + 2]), s_in[r][x + 3]),
                                 s_in[r][x + 4]);
        }
        __syncthreads();

        __half2 nw = __hadd2(__hadd2(__hadd2(__hadd2(s_xr[ty][tx], s_xr[ty + 1][tx]),
                                             s_xr[ty + 2][tx]), s_xr[ty + 3][tx]),
                             s_xr[ty + 4][tx]);
        p0 = p1; p1 = p2; p2 = p3; p3 = p4; p4 = nw;

        if (ip >= 4) {
            int z = z0 + ip - 4;
            int i = z * PLANE + (gy0 + ty) * W + gx0 + tx;
            float2 c = __half22float2(
                __hadd2(__hadd2(__hadd2(__hadd2(p0, p1), p2), p3), p4));
            acc += (double)(c.x * c.x * mask[i]) + (double)(c.y * c.y * mask[i + VOL]);
        }
    }

    sred[tid] = acc;
    __syncthreads();
    for (int s = 128; s > 0; s >>= 1) {
        if (tid < s) sred[tid] += sred[tid + s];
        __syncthreads();
    }
    if (tid == 0) atomicAdd(&g_acc, sred[0]);
}

__global__ void k_finish(float* __restrict__ out) {
    out[0] = (float)(-g_acc);
}

// ---------------------------------------------------------------------------
extern "C" void kernel_launch(void* const* d_in, const int* in_sizes, int n_in,
                              void* d_out, int out_size) {
    const float* f    = (const float*)d_in[0];
    const float* m    = (const float*)d_in[1];
    const float* mask = (const float*)d_in[2];
    float* out = (float*)d_out;

    H4* fm = nullptr; cudaGetSymbolAddress((void**)&fm, g_fm);
    H4* s1 = nullptr; cudaGetSymbolAddress((void**)&s1, g_s1);
    H4* s2 = nullptr; cudaGetSymbolAddress((void**)&s2, g_s2);

    dim3 grd(W / TX2, H / TY2, D / ZC2);   // (5, 20, 20) = 2000 blocks
    const int TB = 256;

    k_zero_acc<<<1, 1>>>();

    // Stage 1: 3D box of raw (F,M) pairs (fills fm cache) -> s1
    k_stage_box<<<grd, TB>>>(LoadRaw4{f, m, fm}, s1);

    // Stage 2: 3D box of (im - u)^2 pairs -> s2
    k_stage_box<<<grd, TB>>>(LoadG4{fm, s1}, s2);

    // Stage 3: 3D box of n_F*n_M + masked -sum(cross^2)
    k_stage_reduce<<<grd, TB>>>(LoadP4{fm, s1, s2}, mask);

    k_finish<<<1, 1>>>(out);
    (void)in_sizes; (void)n_in; (void)out_size;
}